// round 2
// baseline (speedup 1.0000x reference)
#include <cuda_runtime.h>

#define K_STENCIL 27
#define CIN 32
#define COUT 64
#define NODES_PER_BLK 32
#define TPB 256
#define BN_EPS 1e-5f

// ---- device globals (no allocation allowed) ----
__device__ int   g_is64;
__device__ float g_sum[COUT];
__device__ float g_sumsq[COUT];
__device__ float g_scale[COUT];
__device__ float g_bias[COUT];

// Zero accumulators + detect neigh dtype (int64 vs int32).
// If the array is int64 with values in [0, N), every odd 32-bit word is 0.
// If int32, odd words are random indices (P(all zero) ~ 0).
__global__ void prep_kernel(const int* __restrict__ neigh_words, int nelems) {
    int t = threadIdx.x;
    if (t < COUT) { g_sum[t] = 0.f; g_sumsq[t] = 0.f; }
    if (t >= 64 && t < 96) {
        int lane = t - 64;
        int v = 0;
        int limit = nelems < 4096 ? nelems : 4096;   // safe in both dtype cases
        for (int i = 2 * lane + 1; i < limit; i += 64) v |= neigh_words[i];
        v = __reduce_or_sync(0xffffffffu, v);
        if (lane == 0) g_is64 = (v == 0) ? 1 : 0;
    }
}

__global__ void __launch_bounds__(TPB) conv_kernel(
    const float* __restrict__ data, const void* __restrict__ neigh,
    const float* __restrict__ weight, float* __restrict__ out, int N)
{
    __shared__ __align__(16) float sW[CIN * COUT];                 // 8 KB, W_k
    __shared__ __align__(16) float sD[NODES_PER_BLK][CIN];         // 4 KB, gathered rows
    __shared__ int   sidx[NODES_PER_BLK * K_STENCIL];              // 3.4 KB
    __shared__ float rsum[COUT], rsq[COUT];                        // block BN partials

    const int t    = threadIdx.x;
    const int base = blockIdx.x * NODES_PER_BLK;
    const int node = t >> 3;        // 0..31
    const int seg  = t & 7;         // 0..7  (also the output group)
    const int o0   = seg * 8;       // this thread's 8 output channels

    if (t < COUT) { rsum[t] = 0.f; rsq[t] = 0.f; }

    // Load all neighbor indices for this tile once (dtype-dispatched).
    if (g_is64) {
        const long long* nn = (const long long*)neigh;
        for (int i = t; i < NODES_PER_BLK * K_STENCIL; i += TPB) {
            int n = base + i / K_STENCIL;
            sidx[i] = (n < N) ? (int)nn[(long long)n * K_STENCIL + i % K_STENCIL] : -1;
        }
    } else {
        const int* nn = (const int*)neigh;
        for (int i = t; i < NODES_PER_BLK * K_STENCIL; i += TPB) {
            int n = base + i / K_STENCIL;
            sidx[i] = (n < N) ? nn[n * K_STENCIL + i % K_STENCIL] : -1;
        }
    }

    // 8 fp32 accumulators held as 4 packed f32x2.
    unsigned long long acc[4] = {0ull, 0ull, 0ull, 0ull};

    for (int k = 0; k < K_STENCIL; ++k) {
        __syncthreads();
        // Cooperative load of W_k [32x64] into smem (2048 floats = 512 float4).
        {
            const float4* wsrc = (const float4*)(weight + k * CIN * COUT);
            float4* wdst = (float4*)sW;
            wdst[t]       = wsrc[t];
            wdst[t + TPB] = wsrc[t + TPB];
        }
        // Gather: 8 threads per node each fetch one float4 of the neighbor row.
        {
            int idx = sidx[node * K_STENCIL + k];
            float4 v = make_float4(0.f, 0.f, 0.f, 0.f);
            if (idx >= 0)
                v = *(const float4*)(data + (long long)idx * CIN + seg * 4);
            *(float4*)&sD[node][seg * 4] = v;
        }
        __syncthreads();

        // acc[o] += sum_c g[c] * W_k[c][o], 8 outputs via 4 FFMA2 per c.
        #pragma unroll
        for (int c = 0; c < CIN; ++c) {
            float g = sD[node][c];
            unsigned long long gp;
            asm("mov.b64 %0, {%1, %1};" : "=l"(gp) : "r"(__float_as_uint(g)));
            ulonglong2 w01 = *(const ulonglong2*)&sW[c * COUT + o0];       // o0..o0+3
            ulonglong2 w23 = *(const ulonglong2*)&sW[c * COUT + o0 + 4];   // o0+4..o0+7
            asm("fma.rn.f32x2 %0, %1, %2, %0;" : "+l"(acc[0]) : "l"(gp), "l"(w01.x));
            asm("fma.rn.f32x2 %0, %1, %2, %0;" : "+l"(acc[1]) : "l"(gp), "l"(w01.y));
            asm("fma.rn.f32x2 %0, %1, %2, %0;" : "+l"(acc[2]) : "l"(gp), "l"(w23.x));
            asm("fma.rn.f32x2 %0, %1, %2, %0;" : "+l"(acc[3]) : "l"(gp), "l"(w23.y));
        }
    }

    // Write conv output + accumulate BN partial sums.
    const int n = base + node;
    float2 a0 = *(float2*)&acc[0];
    float2 a1 = *(float2*)&acc[1];
    float2 a2 = *(float2*)&acc[2];
    float2 a3 = *(float2*)&acc[3];
    if (n < N) {
        *(float4*)&out[(long long)n * COUT + o0]     = make_float4(a0.x, a0.y, a1.x, a1.y);
        *(float4*)&out[(long long)n * COUT + o0 + 4] = make_float4(a2.x, a2.y, a3.x, a3.y);
        float v[8] = {a0.x, a0.y, a1.x, a1.y, a2.x, a2.y, a3.x, a3.y};
        #pragma unroll
        for (int j = 0; j < 8; ++j) {
            atomicAdd(&rsum[o0 + j], v[j]);
            atomicAdd(&rsq[o0 + j],  v[j] * v[j]);
        }
    }
    __syncthreads();
    if (t < COUT) {
        atomicAdd(&g_sum[t],   rsum[t]);
        atomicAdd(&g_sumsq[t], rsq[t]);
    }
}

__global__ void bn_finalize(const float* __restrict__ gamma,
                            const float* __restrict__ beta, float inv_n) {
    int o = threadIdx.x;
    if (o < COUT) {
        float mean = g_sum[o] * inv_n;
        float var  = g_sumsq[o] * inv_n - mean * mean;
        float s    = gamma[o] * rsqrtf(var + BN_EPS);
        g_scale[o] = s;
        g_bias[o]  = beta[o] - mean * s;
    }
}

__global__ void bn_apply(float* __restrict__ out, int total4) {
    int i      = blockIdx.x * blockDim.x + threadIdx.x;
    int stride = gridDim.x * blockDim.x;
    for (; i < total4; i += stride) {
        float4 v = ((float4*)out)[i];
        int o = (i & 15) * 4;                       // COUT=64 -> 16 float4 per row
        float4 s = *(const float4*)&g_scale[o];
        float4 b = *(const float4*)&g_bias[o];
        v.x = fmaxf(fmaf(v.x, s.x, b.x), 0.f);
        v.y = fmaxf(fmaf(v.y, s.y, b.y), 0.f);
        v.z = fmaxf(fmaf(v.z, s.z, b.z), 0.f);
        v.w = fmaxf(fmaf(v.w, s.w, b.w), 0.f);
        ((float4*)out)[i] = v;
    }
}

extern "C" void kernel_launch(void* const* d_in, const int* in_sizes, int n_in,
                              void* d_out, int out_size) {
    const float* data   = (const float*)d_in[0];
    const void*  neigh  = d_in[1];
    const float* weight = (const float*)d_in[2];
    const float* gamma  = (const float*)d_in[3];
    const float* beta   = (const float*)d_in[4];
    float* out = (float*)d_out;

    int N = in_sizes[0] / CIN;

    prep_kernel<<<1, 128>>>((const int*)neigh, in_sizes[1]);

    int nblk = (N + NODES_PER_BLK - 1) / NODES_PER_BLK;
    conv_kernel<<<nblk, TPB>>>(data, neigh, weight, out, N);

    bn_finalize<<<1, 64>>>(gamma, beta, 1.0f / (float)N);

    int total4 = (N * COUT) / 4;
    int blocks = (total4 + 511) / 512;
    if (blocks > 8192) blocks = 8192;
    bn_apply<<<blocks, 512>>>(out, total4);
}

// round 5
// speedup vs baseline: 3.8511x; 3.8511x over previous
#include <cuda_runtime.h>

#define K_STENCIL 27
#define CIN 32
#define COUT 64
#define M_BLK 64
#define TPB 128
#define BN_EPS 1e-5f

// ---- device globals (no allocation allowed) ----
__device__ int   g_is64;
__device__ float g_sum[COUT];
__device__ float g_sumsq[COUT];
__device__ float g_scale[COUT];
__device__ float g_bias[COUT];

// Zero accumulators + detect neigh dtype (int64 vs int32).
// int64 indices in [0, N): every odd 32-bit word is 0. int32: essentially never.
__global__ void prep_kernel(const int* __restrict__ neigh_words, int nelems) {
    int t = threadIdx.x;
    if (t < COUT) { g_sum[t] = 0.f; g_sumsq[t] = 0.f; }
    if (t >= 64 && t < 96) {
        int lane = t - 64;
        int v = 0;
        int limit = nelems < 4096 ? nelems : 4096;
        for (int i = 2 * lane + 1; i < limit; i += 64) v |= neigh_words[i];
        v = __reduce_or_sync(0xffffffffu, v);
        if (lane == 0) g_is64 = (v == 0) ? 1 : 0;
    }
}

// Block: 64 nodes x 64 couts, 128 threads.
// Thread (cx = t&15, ny = t>>4): 8 nodes (ny*8..+7) x 4 couts (cx*4..+3).
// Accumulators are f32x2 pairs over couts; gathered data is stored DUPLICATED
// in smem so g arrives as natural {g,g} pairs (no packing movs).
__global__ __launch_bounds__(TPB, 6) void conv_kernel(
    const float* __restrict__ data, const void* __restrict__ neigh,
    const float* __restrict__ weight, float* __restrict__ out, int N)
{
    __shared__ __align__(16) float sW[CIN][COUT];        // 8 KB  (W_k)
    __shared__ __align__(16) float sG[CIN][2 * M_BLK];   // 16 KB (gathered, dup)
    __shared__ int   sidx[M_BLK * K_STENCIL];            // 6.75 KB
    __shared__ float rsum[COUT], rsq[COUT];

    const int t    = threadIdx.x;
    const int cx   = t & 15;       // cout group (4 couts)
    const int ny   = t >> 4;       // node group (8 nodes)
    const int base = blockIdx.x * M_BLK;

    if (t < COUT) { rsum[t] = 0.f; rsq[t] = 0.f; }

    // Load neighbor indices for this tile (dtype-dispatched).
    if (g_is64) {
        const long long* nn = (const long long*)neigh;
        for (int i = t; i < M_BLK * K_STENCIL; i += TPB) {
            int n = base + i / K_STENCIL;
            sidx[i] = (n < N) ? (int)nn[(long long)n * K_STENCIL + i % K_STENCIL] : -1;
        }
    } else {
        const int* nn = (const int*)neigh;
        for (int i = t; i < M_BLK * K_STENCIL; i += TPB) {
            int n = base + i / K_STENCIL;
            sidx[i] = (n < N) ? nn[n * K_STENCIL + i % K_STENCIL] : -1;
        }
    }

    // 8 nodes x 2 cout-pairs of packed f32x2 accumulators (32 fp32).
    unsigned long long acc[8][2];
    #pragma unroll
    for (int n = 0; n < 8; ++n) { acc[n][0] = 0ull; acc[n][1] = 0ull; }

    for (int k = 0; k < K_STENCIL; ++k) {
        __syncthreads();
        // W_k [32x64] -> smem: 512 float4, 4 per thread, fully coalesced.
        {
            const float4* wsrc = (const float4*)(weight + k * CIN * COUT);
            float4* wdst = (float4*)sW;
            #pragma unroll
            for (int j = 0; j < 4; ++j) wdst[t + j * TPB] = wsrc[t + j * TPB];
        }
        // Gather + duplicate-store. item = seg*64 + node so that each warp
        // handles ONE seg across 32 consecutive nodes -> STS.64 rows are
        // 256B consecutive (conflict-free).
        #pragma unroll
        for (int j = 0; j < 4; ++j) {
            int item = t + j * TPB;
            int node = item & (M_BLK - 1);
            int seg  = item >> 6;                       // 0..7
            int idx  = sidx[node * K_STENCIL + k];
            float4 v = make_float4(0.f, 0.f, 0.f, 0.f);
            if (idx >= 0)
                v = *(const float4*)(data + (long long)idx * CIN + seg * 4);
            int c0 = seg * 4;
            *(float2*)&sG[c0 + 0][2 * node] = make_float2(v.x, v.x);
            *(float2*)&sG[c0 + 1][2 * node] = make_float2(v.y, v.y);
            *(float2*)&sG[c0 + 2][2 * node] = make_float2(v.z, v.z);
            *(float2*)&sG[c0 + 3][2 * node] = make_float2(v.w, v.w);
        }
        __syncthreads();

        // Inner product: per c, 5 LDS + 16 FFMA2.
        #pragma unroll
        for (int c = 0; c < CIN; ++c) {
            ulonglong2 wu = *(const ulonglong2*)&sW[c][cx * 4];   // {w0,w1},{w2,w3}
            const ulonglong2* gp = (const ulonglong2*)&sG[c][ny * 16];
            ulonglong2 ga = gp[0], gb = gp[1], gc = gp[2], gd = gp[3];
            unsigned long long g0 = ga.x, g1 = ga.y, g2 = gb.x, g3 = gb.y;
            unsigned long long g4 = gc.x, g5 = gc.y, g6 = gd.x, g7 = gd.y;
            asm("fma.rn.f32x2 %0, %1, %2, %0;" : "+l"(acc[0][0]) : "l"(g0), "l"(wu.x));
            asm("fma.rn.f32x2 %0, %1, %2, %0;" : "+l"(acc[0][1]) : "l"(g0), "l"(wu.y));
            asm("fma.rn.f32x2 %0, %1, %2, %0;" : "+l"(acc[1][0]) : "l"(g1), "l"(wu.x));
            asm("fma.rn.f32x2 %0, %1, %2, %0;" : "+l"(acc[1][1]) : "l"(g1), "l"(wu.y));
            asm("fma.rn.f32x2 %0, %1, %2, %0;" : "+l"(acc[2][0]) : "l"(g2), "l"(wu.x));
            asm("fma.rn.f32x2 %0, %1, %2, %0;" : "+l"(acc[2][1]) : "l"(g2), "l"(wu.y));
            asm("fma.rn.f32x2 %0, %1, %2, %0;" : "+l"(acc[3][0]) : "l"(g3), "l"(wu.x));
            asm("fma.rn.f32x2 %0, %1, %2, %0;" : "+l"(acc[3][1]) : "l"(g3), "l"(wu.y));
            asm("fma.rn.f32x2 %0, %1, %2, %0;" : "+l"(acc[4][0]) : "l"(g4), "l"(wu.x));
            asm("fma.rn.f32x2 %0, %1, %2, %0;" : "+l"(acc[4][1]) : "l"(g4), "l"(wu.y));
            asm("fma.rn.f32x2 %0, %1, %2, %0;" : "+l"(acc[5][0]) : "l"(g5), "l"(wu.x));
            asm("fma.rn.f32x2 %0, %1, %2, %0;" : "+l"(acc[5][1]) : "l"(g5), "l"(wu.y));
            asm("fma.rn.f32x2 %0, %1, %2, %0;" : "+l"(acc[6][0]) : "l"(g6), "l"(wu.x));
            asm("fma.rn.f32x2 %0, %1, %2, %0;" : "+l"(acc[6][1]) : "l"(g6), "l"(wu.y));
            asm("fma.rn.f32x2 %0, %1, %2, %0;" : "+l"(acc[7][0]) : "l"(g7), "l"(wu.x));
            asm("fma.rn.f32x2 %0, %1, %2, %0;" : "+l"(acc[7][1]) : "l"(g7), "l"(wu.y));
        }
    }

    // Epilogue: write out + per-thread BN partials (reduced over 8 nodes).
    float s0 = 0.f, s1 = 0.f, s2 = 0.f, s3 = 0.f;
    float q0 = 0.f, q1 = 0.f, q2 = 0.f, q3 = 0.f;
    #pragma unroll
    for (int n = 0; n < 8; ++n) {
        int nn = base + ny * 8 + n;
        if (nn < N) {
            float2 a = *(float2*)&acc[n][0];
            float2 b = *(float2*)&acc[n][1];
            *(float4*)&out[(long long)nn * COUT + cx * 4] =
                make_float4(a.x, a.y, b.x, b.y);
            s0 += a.x; q0 += a.x * a.x;
            s1 += a.y; q1 += a.y * a.y;
            s2 += b.x; q2 += b.x * b.x;
            s3 += b.y; q3 += b.y * b.y;
        }
    }
    atomicAdd(&rsum[cx * 4 + 0], s0);  atomicAdd(&rsq[cx * 4 + 0], q0);
    atomicAdd(&rsum[cx * 4 + 1], s1);  atomicAdd(&rsq[cx * 4 + 1], q1);
    atomicAdd(&rsum[cx * 4 + 2], s2);  atomicAdd(&rsq[cx * 4 + 2], q2);
    atomicAdd(&rsum[cx * 4 + 3], s3);  atomicAdd(&rsq[cx * 4 + 3], q3);
    __syncthreads();
    if (t < COUT) {
        atomicAdd(&g_sum[t],   rsum[t]);
        atomicAdd(&g_sumsq[t], rsq[t]);
    }
}

__global__ void bn_finalize(const float* __restrict__ gamma,
                            const float* __restrict__ beta, float inv_n) {
    int o = threadIdx.x;
    if (o < COUT) {
        float mean = g_sum[o] * inv_n;
        float var  = g_sumsq[o] * inv_n - mean * mean;
        float s    = gamma[o] * rsqrtf(var + BN_EPS);
        g_scale[o] = s;
        g_bias[o]  = beta[o] - mean * s;
    }
}

__global__ void bn_apply(float* __restrict__ out, int total4) {
    int i      = blockIdx.x * blockDim.x + threadIdx.x;
    int stride = gridDim.x * blockDim.x;
    for (; i < total4; i += stride) {
        float4 v = ((float4*)out)[i];
        int o = (i & 15) * 4;                       // COUT=64 -> 16 float4 per row
        float4 s = *(const float4*)&g_scale[o];
        float4 b = *(const float4*)&g_bias[o];
        v.x = fmaxf(fmaf(v.x, s.x, b.x), 0.f);
        v.y = fmaxf(fmaf(v.y, s.y, b.y), 0.f);
        v.z = fmaxf(fmaf(v.z, s.z, b.z), 0.f);
        v.w = fmaxf(fmaf(v.w, s.w, b.w), 0.f);
        ((float4*)out)[i] = v;
    }
}

extern "C" void kernel_launch(void* const* d_in, const int* in_sizes, int n_in,
                              void* d_out, int out_size) {
    const float* data   = (const float*)d_in[0];
    const void*  neigh  = d_in[1];
    const float* weight = (const float*)d_in[2];
    const float* gamma  = (const float*)d_in[3];
    const float* beta   = (const float*)d_in[4];
    float* out = (float*)d_out;

    int N = in_sizes[0] / CIN;

    prep_kernel<<<1, 128>>>((const int*)neigh, in_sizes[1]);

    int nblk = (N + M_BLK - 1) / M_BLK;
    conv_kernel<<<nblk, TPB>>>(data, neigh, weight, out, N);

    bn_finalize<<<1, 64>>>(gamma, beta, 1.0f / (float)N);

    int total4 = (N * COUT) / 4;
    int blocks = (total4 + 511) / 512;
    if (blocks > 8192) blocks = 8192;
    bn_apply<<<blocks, 512>>>(out, total4);
}

// round 9
// speedup vs baseline: 7.9328x; 2.0599x over previous
#include <cuda_runtime.h>
#include <cuda_bf16.h>
#include <cstdint>

#define K_STENCIL 27
#define CIN 32
#define COUT 64
#define M_BLK 128
#define TPB 256
#define BN_EPS 1e-5f
#define MAX_N 320000

// smem row pitch: 64 data bytes + 16 pad -> ldmatrix phase addresses land on
// 8 distinct 16B banks (5*r mod 8 is a permutation of 0..7).
#define APITCH 80

// ---------------- device scratch (no allocation allowed) ----------------
__device__ int   g_is64;
__device__ float g_sum[COUT];
__device__ float g_sumsq[COUT];
__device__ float g_scale[COUT];
__device__ float g_bias[COUT];
__device__ __nv_bfloat16 g_data_hi[MAX_N * CIN];
__device__ __nv_bfloat16 g_data_lo[MAX_N * CIN];
__device__ __nv_bfloat16 g_w_hi[K_STENCIL * COUT * CIN];   // [k][cout][cin]
__device__ __nv_bfloat16 g_w_lo[K_STENCIL * COUT * CIN];

__device__ __forceinline__ uint32_t smem_u32(const void* p) {
    uint32_t a;
    asm("{ .reg .u64 t; cvta.to.shared.u64 t, %1; cvt.u32.u64 %0, t; }"
        : "=r"(a) : "l"(p));
    return a;
}

#define LDMATRIX_X4(r0, r1, r2, r3, addr) \
    asm volatile("ldmatrix.sync.aligned.m8n8.x4.shared.b16 {%0,%1,%2,%3}, [%4];" \
        : "=r"(r0), "=r"(r1), "=r"(r2), "=r"(r3) : "r"(addr))

#define MMA_BF16(d, a0, a1, a2, a3, b0, b1) \
    asm volatile("mma.sync.aligned.m16n8k16.row.col.f32.bf16.bf16.f32 " \
        "{%0,%1,%2,%3}, {%4,%5,%6,%7}, {%8,%9}, {%0,%1,%2,%3};" \
        : "+f"((d)[0]), "+f"((d)[1]), "+f"((d)[2]), "+f"((d)[3]) \
        : "r"(a0), "r"(a1), "r"(a2), "r"(a3), "r"(b0), "r"(b1))

// ---------------- small kernels ----------------
__global__ void prep_kernel(const int* __restrict__ neigh_words, int nelems) {
    int t = threadIdx.x;
    if (t < COUT) { g_sum[t] = 0.f; g_sumsq[t] = 0.f; }
    if (t >= 64 && t < 96) {
        int lane = t - 64;
        int v = 0;
        int limit = nelems < 4096 ? nelems : 4096;
        for (int i = 2 * lane + 1; i < limit; i += 64) v |= neigh_words[i];
        v = __reduce_or_sync(0xffffffffu, v);
        if (lane == 0) g_is64 = (v == 0) ? 1 : 0;
    }
}

__global__ void cvt_data_kernel(const float* __restrict__ data, int total4) {
    int i = blockIdx.x * blockDim.x + threadIdx.x;
    int stride = gridDim.x * blockDim.x;
    for (; i < total4; i += stride) {
        float4 x = ((const float4*)data)[i];
        __nv_bfloat16 h0 = __float2bfloat16_rn(x.x);
        __nv_bfloat16 h1 = __float2bfloat16_rn(x.y);
        __nv_bfloat16 h2 = __float2bfloat16_rn(x.z);
        __nv_bfloat16 h3 = __float2bfloat16_rn(x.w);
        __nv_bfloat16 l0 = __float2bfloat16_rn(x.x - __bfloat162float(h0));
        __nv_bfloat16 l1 = __float2bfloat16_rn(x.y - __bfloat162float(h1));
        __nv_bfloat16 l2 = __float2bfloat16_rn(x.z - __bfloat162float(h2));
        __nv_bfloat16 l3 = __float2bfloat16_rn(x.w - __bfloat162float(h3));
        uint2 hp, lp;
        hp.x = ((uint32_t)__bfloat16_as_ushort(h1) << 16) | __bfloat16_as_ushort(h0);
        hp.y = ((uint32_t)__bfloat16_as_ushort(h3) << 16) | __bfloat16_as_ushort(h2);
        lp.x = ((uint32_t)__bfloat16_as_ushort(l1) << 16) | __bfloat16_as_ushort(l0);
        lp.y = ((uint32_t)__bfloat16_as_ushort(l3) << 16) | __bfloat16_as_ushort(l2);
        *(uint2*)&g_data_hi[i * 4] = hp;
        *(uint2*)&g_data_lo[i * 4] = lp;
    }
}

__global__ void cvt_weight_kernel(const float* __restrict__ weight) {
    int i = blockIdx.x * blockDim.x + threadIdx.x;
    int total = K_STENCIL * COUT * CIN;
    if (i < total) {
        int k = i / (COUT * CIN);
        int r = i - k * (COUT * CIN);
        int n = r >> 5;            // cout
        int c = r & 31;            // cin
        float x = weight[(k * CIN + c) * COUT + n];
        __nv_bfloat16 h = __float2bfloat16_rn(x);
        __nv_bfloat16 l = __float2bfloat16_rn(x - __bfloat162float(h));
        g_w_hi[i] = h;
        g_w_lo[i] = l;
    }
}

// ---------------- main conv kernel: warp-level bf16 HMMA, hi/lo split ----
// Block: 128 nodes x 64 couts, 8 warps; warp wm owns nodes [wm*16, wm*16+16).
// Per stencil k: all threads gather A rows (hi+lo) and W_k into smem, then
// each warp runs 2 k16-steps x 8 n-tiles x 3 combos = 48 mma.m16n8k16.
__global__ void __launch_bounds__(TPB, 3) conv_kernel(
    const void* __restrict__ neigh, float* __restrict__ out, int N)
{
    __shared__ __align__(16) char sA[2 * M_BLK * APITCH];   // hi, lo (20.0 KB)
    __shared__ __align__(16) char sB[2 * COUT * APITCH];    // hi, lo (10.0 KB)
    __shared__ int   sidx[K_STENCIL * M_BLK];               // 13.5 KB
    __shared__ float rsum[COUT], rsq[COUT];

    const int t    = threadIdx.x;
    const int wm   = t >> 5;
    const int l    = t & 31;
    const int base = blockIdx.x * M_BLK;

    if (t < COUT) { rsum[t] = 0.f; rsq[t] = 0.f; }

    // Preload all neighbor indices, [k][node] layout (dtype-dispatched).
    if (g_is64) {
        const long long* nn = (const long long*)neigh;
        for (int i = t; i < K_STENCIL * M_BLK; i += TPB) {
            int k = i >> 7, node = i & 127;
            int n = base + node;
            sidx[i] = (n < N) ? (int)nn[(long long)n * K_STENCIL + k] : -1;
        }
    } else {
        const int* nn = (const int*)neigh;
        for (int i = t; i < K_STENCIL * M_BLK; i += TPB) {
            int k = i >> 7, node = i & 127;
            int n = base + node;
            sidx[i] = (n < N) ? nn[n * K_STENCIL + k] : -1;
        }
    }

    const uint32_t sA_u = smem_u32(sA);
    const uint32_t sB_u = smem_u32(sB);
    // ldmatrix lane address offsets (row part), computed once.
    const uint32_t a_off = sA_u + (uint32_t)((wm * 16 + (l & 15)) * APITCH
                                             + ((l >> 4) & 1) * 16);
    const uint32_t b_off = sB_u + (uint32_t)(((l >> 4) * 8 + (l & 7)) * APITCH
                                             + ((l >> 3) & 1) * 16);

    float acc[8][4];
    #pragma unroll
    for (int nt = 0; nt < 8; ++nt)
        #pragma unroll
        for (int j = 0; j < 4; ++j) acc[nt][j] = 0.f;

    const int gnode = t >> 1;       // gather: row per thread pair
    const int ghalf = t & 1;        // 32B half of the 64B row

    for (int k = 0; k < K_STENCIL; ++k) {
        __syncthreads();
        // ---- gather A (hi+lo): 128 rows x 64 B each ----
        {
            int idx = sidx[k * M_BLK + gnode];
            uint4 h0, h1, l0, l1;
            if (idx >= 0) {
                const uint4* ph = (const uint4*)(g_data_hi + (long long)idx * CIN)
                                  + ghalf * 2;
                const uint4* pl = (const uint4*)(g_data_lo + (long long)idx * CIN)
                                  + ghalf * 2;
                h0 = ph[0]; h1 = ph[1];
                l0 = pl[0]; l1 = pl[1];
            } else {
                h0 = h1 = l0 = l1 = make_uint4(0, 0, 0, 0);
            }
            char* pa = sA + gnode * APITCH + ghalf * 32;
            *(uint4*)(pa)      = h0;
            *(uint4*)(pa + 16) = h1;
            *(uint4*)(pa + M_BLK * APITCH)      = l0;
            *(uint4*)(pa + M_BLK * APITCH + 16) = l1;
        }
        // ---- load W_k (hi+lo): 64 rows x 64 B each ----
        {
            int n = t >> 2, q = t & 3;               // 256 thr = 64 rows x 4 chunks
            const uint4* wh = (const uint4*)(g_w_hi + (k * COUT + n) * CIN) + q;
            const uint4* wl = (const uint4*)(g_w_lo + (k * COUT + n) * CIN) + q;
            char* pb = sB + n * APITCH + q * 16;
            *(uint4*)pb = *wh;
            *(uint4*)(pb + COUT * APITCH) = *wl;
        }
        __syncthreads();

        // ---- compute: 2 k16-steps, 8 n-tiles, 3 combos ----
        #pragma unroll
        for (int cs = 0; cs < 2; ++cs) {
            uint32_t ah0, ah1, ah2, ah3, al0, al1, al2, al3;
            LDMATRIX_X4(ah0, ah1, ah2, ah3, a_off + cs * 32);
            LDMATRIX_X4(al0, al1, al2, al3, a_off + cs * 32 + M_BLK * APITCH);
            #pragma unroll
            for (int ntp = 0; ntp < 4; ++ntp) {
                uint32_t bh0, bh1, bh2, bh3, bl0, bl1, bl2, bl3;
                uint32_t ba = b_off + ntp * (16 * APITCH) + cs * 32;
                LDMATRIX_X4(bh0, bh1, bh2, bh3, ba);
                LDMATRIX_X4(bl0, bl1, bl2, bl3, ba + COUT * APITCH);
                MMA_BF16(acc[2 * ntp],     ah0, ah1, ah2, ah3, bh0, bh1);
                MMA_BF16(acc[2 * ntp],     ah0, ah1, ah2, ah3, bl0, bl1);
                MMA_BF16(acc[2 * ntp],     al0, al1, al2, al3, bh0, bh1);
                MMA_BF16(acc[2 * ntp + 1], ah0, ah1, ah2, ah3, bh2, bh3);
                MMA_BF16(acc[2 * ntp + 1], ah0, ah1, ah2, ah3, bl2, bl3);
                MMA_BF16(acc[2 * ntp + 1], al0, al1, al2, al3, bh2, bh3);
            }
        }
    }

    // ---- epilogue: write out + BN partials ----
    // Fragment c layout (m16n8): lane l holds rows {l>>2, (l>>2)+8} (local),
    // cols {2*(l&3), 2*(l&3)+1} within the tile.
    const int r0 = base + wm * 16 + (l >> 2);
    const int r1 = r0 + 8;
    #pragma unroll
    for (int nt = 0; nt < 8; ++nt) {
        int c0 = nt * 8 + 2 * (l & 3);
        if (r0 < N)
            *(float2*)&out[(long long)r0 * COUT + c0] =
                make_float2(acc[nt][0], acc[nt][1]);
        if (r1 < N)
            *(float2*)&out[(long long)r1 * COUT + c0] =
                make_float2(acc[nt][2], acc[nt][3]);
        // rows >= N hold exact zeros (zero A rows) -> safe to include in sums
        float s0 = acc[nt][0] + acc[nt][2];
        float s1 = acc[nt][1] + acc[nt][3];
        float q0 = acc[nt][0] * acc[nt][0] + acc[nt][2] * acc[nt][2];
        float q1 = acc[nt][1] * acc[nt][1] + acc[nt][3] * acc[nt][3];
        #pragma unroll
        for (int m = 4; m < 32; m <<= 1) {
            s0 += __shfl_xor_sync(0xffffffffu, s0, m);
            s1 += __shfl_xor_sync(0xffffffffu, s1, m);
            q0 += __shfl_xor_sync(0xffffffffu, q0, m);
            q1 += __shfl_xor_sync(0xffffffffu, q1, m);
        }
        if (l < 4) {
            atomicAdd(&rsum[c0],     s0);
            atomicAdd(&rsum[c0 + 1], s1);
            atomicAdd(&rsq[c0],      q0);
            atomicAdd(&rsq[c0 + 1],  q1);
        }
    }
    __syncthreads();
    if (t < COUT) {
        atomicAdd(&g_sum[t],   rsum[t]);
        atomicAdd(&g_sumsq[t], rsq[t]);
    }
}

__global__ void bn_finalize(const float* __restrict__ gamma,
                            const float* __restrict__ beta, float inv_n) {
    int o = threadIdx.x;
    if (o < COUT) {
        float mean = g_sum[o] * inv_n;
        float var  = g_sumsq[o] * inv_n - mean * mean;
        float s    = gamma[o] * rsqrtf(var + BN_EPS);
        g_scale[o] = s;
        g_bias[o]  = beta[o] - mean * s;
    }
}

__global__ void bn_apply(float* __restrict__ out, int total4) {
    int i      = blockIdx.x * blockDim.x + threadIdx.x;
    int stride = gridDim.x * blockDim.x;
    for (; i < total4; i += stride) {
        float4 v = ((float4*)out)[i];
        int o = (i & 15) * 4;
        float4 s = *(const float4*)&g_scale[o];
        float4 b = *(const float4*)&g_bias[o];
        v.x = fmaxf(fmaf(v.x, s.x, b.x), 0.f);
        v.y = fmaxf(fmaf(v.y, s.y, b.y), 0.f);
        v.z = fmaxf(fmaf(v.z, s.z, b.z), 0.f);
        v.w = fmaxf(fmaf(v.w, s.w, b.w), 0.f);
        ((float4*)out)[i] = v;
    }
}

extern "C" void kernel_launch(void* const* d_in, const int* in_sizes, int n_in,
                              void* d_out, int out_size) {
    const float* data   = (const float*)d_in[0];
    const void*  neigh  = d_in[1];
    const float* weight = (const float*)d_in[2];
    const float* gamma  = (const float*)d_in[3];
    const float* beta   = (const float*)d_in[4];
    float* out = (float*)d_out;

    int N = in_sizes[0] / CIN;

    prep_kernel<<<1, 128>>>((const int*)neigh, in_sizes[1]);

    int total4 = (N * CIN) / 4;
    cvt_data_kernel<<<2048, 256>>>(data, total4);
    cvt_weight_kernel<<<(K_STENCIL * COUT * CIN + 255) / 256, 256>>>(weight);

    int nblk = (N + M_BLK - 1) / M_BLK;
    conv_kernel<<<nblk, TPB>>>(neigh, out, N);

    bn_finalize<<<1, 64>>>(gamma, beta, 1.0f / (float)N);

    int out4 = (N * COUT) / 4;
    int blocks = (out4 + 511) / 512;
    if (blocks > 8192) blocks = 8192;
    bn_apply<<<blocks, 512>>>(out, out4);
}